// round 1
// baseline (speedup 1.0000x reference)
#include <cuda_runtime.h>
#include <cstdint>
#include <cstddef>

#define NN 1024
#define DF 16
#define CHUNK 32
#define RSTR 34                 // staged row stride in floats (136 B, 8B-aligned)
#define WROWS 64                // rows per warp (2 per lane)
#define NWARP 8
#define NCHUNK (NN / CHUNK)     // 32
#define SMEM_F_FLOATS (NN * DF)                    // 16384 floats = 64 KB
#define WARP_BUF_FLOATS (WROWS * RSTR)             // 2176 floats = 8704 B
#define SMEM_TOTAL_BYTES ((SMEM_F_FLOATS + NWARP * 2 * WARP_BUF_FLOATS) * 4)  // 204800 B

// ---- f32x2 packed-math helpers (FFMA2 is PTX-only on sm_103a) ----
__device__ __forceinline__ unsigned long long pk2(float x, float y) {
    unsigned long long r;
    asm("mov.b64 %0, {%1, %2};" : "=l"(r) : "f"(x), "f"(y));
    return r;
}
__device__ __forceinline__ void fma2(unsigned long long& d, unsigned long long a, unsigned long long b) {
    asm("fma.rn.f32x2 %0, %1, %2, %0;" : "+l"(d) : "l"(a), "l"(b));
}
__device__ __forceinline__ void upk2(unsigned long long v, float& x, float& y) {
    asm("mov.b64 {%0, %1}, %2;" : "=f"(x), "=f"(y) : "l"(v));
}
__device__ __forceinline__ void cp8(unsigned dst, const float* src) {
    asm volatile("cp.async.ca.shared.global [%0], [%1], 8;" :: "r"(dst), "l"(src));
}

__global__ void zero_out_kernel(float* o) { o[threadIdx.x] = 0.0f; }

__global__ void __launch_bounds__(256, 1)
graph_loss_kernel(const float* __restrict__ A,
                  const float* __restrict__ F,
                  float* __restrict__ out) {
    extern __shared__ float smem[];
    const int tid  = threadIdx.x;
    const int lane = tid & 31;
    const int wid  = tid >> 5;
    const int b    = blockIdx.x >> 1;   // batch
    const int blk  = blockIdx.x & 1;    // which 512-row half

    float* F_s = smem;  // [1024][16] fp32, resident

    // ---- Load F[b] into shared (64 KB), vectorized ----
    {
        const float4* src = reinterpret_cast<const float4*>(F + (size_t)b * NN * DF);
        float4* dst = reinterpret_cast<float4*>(F_s);
        #pragma unroll
        for (int i = 0; i < (NN * DF / 4) / 256; ++i)
            dst[tid + i * 256] = src[tid + i * 256];
    }
    __syncthreads();

    const int row0 = blk * (NWARP * WROWS) + wid * WROWS;   // first row (within batch) of this warp
    const float* Ab = A + (size_t)b * NN * NN + (size_t)row0 * NN;

    const unsigned sbase = (unsigned)__cvta_generic_to_shared(smem);
    const unsigned abase = sbase + SMEM_F_FLOATS * 4 + wid * (2 * WARP_BUF_FLOATS * 4);
    float* abuf = smem + SMEM_F_FLOATS + wid * (2 * WARP_BUF_FLOATS);

    // Accumulators: per lane, 2 rows. AF as 8 f32x2 pairs each; {deg, sum(a^2)} packed.
    unsigned long long acc0[8], acc1[8];
    unsigned long long dss0 = 0ull, dss1 = 0ull;
    #pragma unroll
    for (int k = 0; k < 8; ++k) { acc0[k] = 0ull; acc1[k] = 0ull; }

    const int rl = lane >> 4;   // 0/1: which row of the lane-pair group
    const int u  = lane & 15;   // 8-byte unit within a 128B row-chunk

    // ---- cp.async issue of one 64x32 A chunk into buffer bufi ----
    auto issue = [&](int c, int bufi) {
        const unsigned d0 = abase + bufi * (WARP_BUF_FLOATS * 4) + rl * (RSTR * 4) + u * 8;
        const float* s0 = Ab + c * CHUNK + rl * NN + u * 2;
        #pragma unroll
        for (int k = 0; k < 32; ++k)
            cp8(d0 + k * (2 * RSTR * 4), s0 + k * (2 * NN));
        asm volatile("cp.async.commit_group;");
    };

    issue(0, 0);

    for (int c = 0; c < NCHUNK; ++c) {
        const int cur = c & 1;
        if (c < NCHUNK - 1) {
            issue(c + 1, cur ^ 1);
            asm volatile("cp.async.wait_group 1;" ::: "memory");
        } else {
            asm volatile("cp.async.wait_group 0;" ::: "memory");
        }
        __syncwarp();

        const float* buf  = abuf + cur * WARP_BUF_FLOATS;
        const float* fcol = F_s + c * CHUNK * DF;

        #pragma unroll 4
        for (int j = 0; j < CHUNK; ++j) {
            // F[j] broadcast: 4x LDS.128 delivering f32x2 pairs directly
            const ulonglong2* fp = reinterpret_cast<const ulonglong2*>(fcol + j * DF);
            ulonglong2 q0 = fp[0];
            ulonglong2 q1 = fp[1];
            ulonglong2 q2 = fp[2];
            ulonglong2 q3 = fp[3];

            float a0 = buf[lane * RSTR + j];
            float a1 = buf[(lane + 32) * RSTR + j];
            unsigned long long pa0 = pk2(a0, a0);
            unsigned long long pa1 = pk2(a1, a1);

            // {deg, ss} += {a, a} * {1, a}
            fma2(dss0, pa0, pk2(1.0f, a0));
            fma2(dss1, pa1, pk2(1.0f, a1));

            fma2(acc0[0], pa0, q0.x); fma2(acc0[1], pa0, q0.y);
            fma2(acc0[2], pa0, q1.x); fma2(acc0[3], pa0, q1.y);
            fma2(acc0[4], pa0, q2.x); fma2(acc0[5], pa0, q2.y);
            fma2(acc0[6], pa0, q3.x); fma2(acc0[7], pa0, q3.y);

            fma2(acc1[0], pa1, q0.x); fma2(acc1[1], pa1, q0.y);
            fma2(acc1[2], pa1, q1.x); fma2(acc1[3], pa1, q1.y);
            fma2(acc1[4], pa1, q2.x); fma2(acc1[5], pa1, q2.y);
            fma2(acc1[6], pa1, q3.x); fma2(acc1[7], pa1, q3.y);
        }
        __syncwarp();
    }

    // ---- Finalize: per-row loss contribution, warp reduce, atomic per batch ----
    const float c1 = 0.2f / (1024.0f * 1024.0f);   // smoothness / N^2
    const float c2 = 0.1f / 1024.0f;               // degree / N
    const float c3 = 0.1f / (1024.0f * 1024.0f);   // sparsity / N^2

    float contrib = 0.0f;
    #pragma unroll
    for (int r = 0; r < 2; ++r) {
        float deg, ss;
        upk2(r ? dss1 : dss0, deg, ss);
        const int node = row0 + lane + r * 32;
        const float* fr = F_s + node * DF;
        float t1 = 0.0f, t2 = 0.0f;
        #pragma unroll
        for (int k = 0; k < 8; ++k) {
            float af0, af1;
            upk2(r ? acc1[k] : acc0[k], af0, af1);
            float f0 = fr[2 * k], f1 = fr[2 * k + 1];
            t1 += f0 * f0 + f1 * f1;     // ||f_n||^2
            t2 += f0 * af0 + f1 * af1;   // <f_n, (A F)_n>
        }
        contrib += c1 * (deg * t1 - t2) - c2 * logf(deg + 1e-12f) + c3 * ss;
    }

    #pragma unroll
    for (int o = 16; o; o >>= 1)
        contrib += __shfl_xor_sync(0xffffffffu, contrib, o);
    if (lane == 0)
        atomicAdd(out + b, contrib);
}

extern "C" void kernel_launch(void* const* d_in, const int* in_sizes, int n_in,
                              void* d_out, int out_size) {
    const float* A = (const float*)d_in[0];   // out_adj [64,1024,1024]
    const float* F = (const float*)d_in[1];   // features [64,1024,16]
    float* out = (float*)d_out;               // [64]

    static bool attr_set = false;
    if (!attr_set) {
        cudaFuncSetAttribute(graph_loss_kernel,
                             cudaFuncAttributeMaxDynamicSharedMemorySize,
                             SMEM_TOTAL_BYTES);
        attr_set = true;
    }

    zero_out_kernel<<<1, 64>>>(out);
    graph_loss_kernel<<<128, 256, SMEM_TOTAL_BYTES>>>(A, F, out);
}